// round 1
// baseline (speedup 1.0000x reference)
#include <cuda_runtime.h>
#include <cuda_fp16.h>

#define H       2048
#define NSEQ    4096
#define TSTEPS  4098        // N + 2 rows of xs
#define GRID    148
#define THREADS 512
#define MAXR    56          // 4 gates * 14 h-indices max per block

// Hidden state published between blocks, fp16, double-buffered.
__device__ __align__(16) __half g_h[2][H];
// Decentralized barrier flags, padded to 32B to spread L2 lines.
__device__ unsigned g_flag[GRID * 8];

struct SmemLayout {
    __half w[MAXR][H];      // 229376 B : fp16 W_hh rows owned by this block
    float  dots[MAXR];      // per-row dot results
    float  wih[MAXR][3];    // W_ih rows for this block
    float  bias[MAXR];      // b_ih + b_hh
};

__global__ void __launch_bounds__(THREADS, 1)
lstm_persistent_kernel(const float* __restrict__ seq,
                       const float* __restrict__ Wih,
                       const float* __restrict__ Whh,
                       const float* __restrict__ bih,
                       const float* __restrict__ bhh,
                       float* __restrict__ out)
{
    extern __shared__ char smem_raw[];
    SmemLayout& S = *reinterpret_cast<SmemLayout*>(smem_raw);

    const int b    = blockIdx.x;
    const int tid  = threadIdx.x;
    const int lane = tid & 31;
    const int wrp  = tid >> 5;

    // Block b owns h indices j = b + GRID*i, i in [0, nj)
    const int nj = (H - 1 - b) / GRID + 1;   // 14 for b<124, else 13
    const int R  = 4 * nj;                   // rows of W_hh this block owns

    // ---- One-time init: load & convert this block's W_hh rows to fp16 SMEM ----
    for (int r = 0; r < R; r++) {
        const int g    = r / nj;
        const int i    = r - g * nj;
        const int grow = g * H + b + GRID * i;
        const float* src = Whh + (size_t)grow * H;
        for (int k = tid; k < H; k += THREADS)
            S.w[r][k] = __float2half_rn(src[k]);
        if (tid == 0) S.bias[r] = bih[grow] + bhh[grow];
        if (tid < 3)  S.wih[r][tid] = Wih[grow * 3 + tid];
    }
    __syncthreads();

    // Per-launch barrier base (all flags end every launch at the same value).
    const unsigned flag_base = *(volatile unsigned*)&g_flag[b * 8];

    float cj = 0.0f;                 // cell state for combine thread tid < nj
    float* hs_out = out + H;         // out[0:H] = final h, then hs (4097 x H)

    for (int t = 0; t < TSTEPS; t++) {
        // ---------- matvec: dots[r] = sum_k W[r][k] * h_prev[k] ----------
        if (t > 0) {
            const uint2* h2g = reinterpret_cast<const uint2*>(g_h[t & 1]);
            // Each lane covers half2 indices {64m + 2*lane, +1}, m = 0..15
            __half2 hh[32];
#pragma unroll
            for (int m = 0; m < 16; m++) {
                uint2 v = __ldcg(h2g + 32 * m + lane);
                hh[2 * m]     = *reinterpret_cast<const __half2*>(&v.x);
                hh[2 * m + 1] = *reinterpret_cast<const __half2*>(&v.y);
            }
            for (int r = wrp; r < R; r += (THREADS / 32)) {
                const uint2* wrow = reinterpret_cast<const uint2*>(&S.w[r][0]);
                __half2 a0 = __float2half2_rn(0.f);
                __half2 a1 = a0, a2 = a0, a3 = a0;
#pragma unroll
                for (int m = 0; m < 16; m += 2) {
                    uint2 w0 = wrow[32 * m + lane];
                    a0 = __hfma2(*reinterpret_cast<const __half2*>(&w0.x), hh[2 * m],     a0);
                    a1 = __hfma2(*reinterpret_cast<const __half2*>(&w0.y), hh[2 * m + 1], a1);
                    uint2 w1 = wrow[32 * (m + 1) + lane];
                    a2 = __hfma2(*reinterpret_cast<const __half2*>(&w1.x), hh[2 * m + 2], a2);
                    a3 = __hfma2(*reinterpret_cast<const __half2*>(&w1.y), hh[2 * m + 3], a3);
                }
                float2 f0 = __half22float2(__hadd2(a0, a1));
                float2 f1 = __half22float2(__hadd2(a2, a3));
                float s = (f0.x + f1.x) + (f0.y + f1.y);
#pragma unroll
                for (int off = 16; off; off >>= 1)
                    s += __shfl_xor_sync(0xffffffffu, s, off);
                if (lane == 0) S.dots[r] = s;
            }
        }
        __syncthreads();

        // ---------- combine: gates -> (c, h), publish h ----------
        if (tid < nj) {
            const int j = b + GRID * tid;
            float x0, x1, x2;
            if (t == 0 || t == TSTEPS - 1) { x0 = 0.f; x1 = 0.f; x2 = 1.f; }
            else {
                const float* sp = seq + (size_t)(t - 1) * 3;
                x0 = sp[0]; x1 = sp[1]; x2 = sp[2];
            }
            float gate[4];
#pragma unroll
            for (int g = 0; g < 4; g++) {
                const int r = g * nj + tid;
                float d = (t > 0) ? S.dots[r] : 0.f;
                gate[g] = d + S.bias[r]
                        + S.wih[r][0] * x0 + S.wih[r][1] * x1 + S.wih[r][2] * x2;
            }
            const float ig = 1.f / (1.f + expf(-gate[0]));
            const float fg = 1.f / (1.f + expf(-gate[1]));
            const float gg = tanhf(gate[2]);
            const float og = 1.f / (1.f + expf(-gate[3]));
            cj = fg * cj + ig * gg;
            const float hj = og * tanhf(cj);

            g_h[(t + 1) & 1][j] = __float2half_rn(hj);
            if (t >= 1)          hs_out[(size_t)(t - 1) * H + j] = hj;
            if (t == TSTEPS - 1) out[j] = hj;
        }

        // ---------- grid barrier (skip after last step) ----------
        if (t < TSTEPS - 1) {
            __syncthreads();                       // combine stores done block-wide
            const unsigned target = flag_base + (unsigned)t + 1u;
            if (tid == 0) {
                __threadfence();                   // release h writes
                *(volatile unsigned*)&g_flag[b * 8] = target;
            }
            if (tid < GRID) {
                volatile unsigned* f = &g_flag[tid * 8];
                while ((int)(*f - target) < 0) { }
            }
            __threadfence();                       // acquire remote h writes
            __syncthreads();
        }
    }
}

extern "C" void kernel_launch(void* const* d_in, const int* in_sizes, int n_in,
                              void* d_out, int out_size)
{
    const float* seq = (const float*)d_in[0];
    const float* Wih = (const float*)d_in[1];
    const float* Whh = (const float*)d_in[2];
    const float* bih = (const float*)d_in[3];
    const float* bhh = (const float*)d_in[4];
    float* out = (float*)d_out;

    const size_t smem = sizeof(SmemLayout);
    cudaFuncSetAttribute(lstm_persistent_kernel,
                         cudaFuncAttributeMaxDynamicSharedMemorySize, (int)smem);
    lstm_persistent_kernel<<<GRID, THREADS, smem>>>(seq, Wih, Whh, bih, bhh, out);
}